// round 14
// baseline (speedup 1.0000x reference)
#include <cuda_runtime.h>
#include <cuda_bf16.h>
#include <cstdint>

// ---------------------------------------------------------------------------
// GATv2 GNN, 3 layers. CSR-by-dst; warp-per-node FUSED logits+softmax+aggregate.
// R14: cp.async double-buffered tf32 GEMM (raw-fp32 truncation, 2-stage pipeline).
// ---------------------------------------------------------------------------

#define MAX_N 50000
#define MAX_E 800000

__device__ float g_xl[MAX_N * 256];
__device__ float g_xr[MAX_N * 256];
__device__ float g_h [MAX_N * 256];
__device__ int   g_rowptr[MAX_N + 1];
__device__ int   g_cursor[MAX_N];
__device__ int   g_deg   [MAX_N];
__device__ int   g_csrsrc[MAX_E];

// ---------------- CSR build ----------------

__global__ void zero_kernel(int* __restrict__ p, int n) {
    int i = blockIdx.x * blockDim.x + threadIdx.x;
    if (i < n) p[i] = 0;
}

__global__ void hist_kernel(const int* __restrict__ dst, int E, int N, int* __restrict__ deg) {
    int e = blockIdx.x * blockDim.x + threadIdx.x;
    if (e >= E) return;
    int d = dst[e];
    if (d >= 0 && d < N) atomicAdd(&deg[d], 1);
}

__global__ void scan_kernel(const int* __restrict__ deg, int* __restrict__ rowptr,
                            int* __restrict__ cursor, int n) {
    __shared__ int warp_s[32];
    __shared__ int s_carry;
    int lane = threadIdx.x & 31, wid = threadIdx.x >> 5;
    if (threadIdx.x == 0) s_carry = 0;
    __syncthreads();
    for (int base = 0; base < n; base += 1024) {
        int i = base + threadIdx.x;
        int v = (i < n) ? deg[i] : 0;
        int x = v;
        #pragma unroll
        for (int o = 1; o < 32; o <<= 1) { int t = __shfl_up_sync(0xffffffffu, x, o); if (lane >= o) x += t; }
        if (lane == 31) warp_s[wid] = x;
        __syncthreads();
        if (wid == 0) {
            int y = warp_s[lane];
            #pragma unroll
            for (int o = 1; o < 32; o <<= 1) { int t = __shfl_up_sync(0xffffffffu, y, o); if (lane >= o) y += t; }
            warp_s[lane] = y;
        }
        __syncthreads();
        int off = s_carry + (wid ? warp_s[wid - 1] : 0);
        if (i < n) {
            int excl = off + x - v;
            rowptr[i] = excl;
            cursor[i] = excl;
        }
        int total = warp_s[31];
        __syncthreads();
        if (threadIdx.x == 0) s_carry += total;
        __syncthreads();
    }
    if (threadIdx.x == 0) rowptr[n] = s_carry;
}

__global__ void scatter_kernel(const int* __restrict__ src, const int* __restrict__ dst,
                               int E, int N, int* __restrict__ cursor,
                               int* __restrict__ csrsrc) {
    int e = blockIdx.x * blockDim.x + threadIdx.x;
    if (e >= E) return;
    int d = dst[e];
    if (d < 0 || d >= N) return;
    int s = src[e];
    int p = atomicAdd(&cursor[d], 1);
    csrsrc[p] = s;
}

// ---------------- tf32 GEMM: 128x128x16, cp.async double-buffered ----------------

#define TBM 128
#define TBN 128
#define TBK 16
#define TPAD 136

__device__ __forceinline__ void cpa4(uint32_t saddr, const float* g, bool pred) {
    int sz = pred ? 4 : 0;
    asm volatile("cp.async.ca.shared.global [%0], [%1], 4, %2;"
                 :: "r"(saddr), "l"(g), "r"(sz));
}
__device__ __forceinline__ void cpa16(uint32_t saddr, const float* g, bool pred) {
    int sz = pred ? 16 : 0;
    asm volatile("cp.async.cg.shared.global [%0], [%1], 16, %2;"
                 :: "r"(saddr), "l"(g), "r"(sz));
}

__global__ __launch_bounds__(256) void gemm_tf32_kernel(
    const float* __restrict__ A,
    const float* __restrict__ B0, const float* __restrict__ B1,
    float* __restrict__ C0, float* __restrict__ C1,
    int M, int K, int N) {
    const float* __restrict__ B = blockIdx.z ? B1 : B0;
    float* __restrict__ C = blockIdx.z ? C1 : C0;

    __shared__ float As[2][TBK][TPAD];
    __shared__ float Bs[2][TBK][TPAD];

    int tid = threadIdx.x;
    int wid = tid >> 5, lane = tid & 31;
    int m0 = blockIdx.y * TBM, n0 = blockIdx.x * TBN;
    int warp_m = (wid >> 1) << 5;
    int warp_n = (wid & 1) << 6;

    float c[2][8][4];
    #pragma unroll
    for (int i = 0; i < 2; i++)
        #pragma unroll
        for (int j = 0; j < 8; j++)
            #pragma unroll
            for (int q = 0; q < 4; q++) c[i][j][q] = 0.f;

    int ak = tid & 15, am = tid >> 4;     // A: column ak, rows am+16i
    int bk = tid >> 4, bq = tid & 15;     // B: row bk, float4 quads bq, bq+16
    int r = lane & 3, g = lane >> 2;

    int nIter = (K + TBK - 1) / TBK;

    uint32_t sA[2], sB[2];
    sA[0] = (uint32_t)__cvta_generic_to_shared(&As[0][0][0]);
    sA[1] = (uint32_t)__cvta_generic_to_shared(&As[1][0][0]);
    sB[0] = (uint32_t)__cvta_generic_to_shared(&Bs[0][0][0]);
    sB[1] = (uint32_t)__cvta_generic_to_shared(&Bs[1][0][0]);

    // issue loads for k-tile `it` into stage s
    auto issue = [&](int it, int s) {
        int k0 = it * TBK;
        bool kA = (k0 + ak) < K;
        const float* gA = A + (long)(m0 + am) * K + k0 + ak;
        uint32_t dA = sA[s] + ((ak * TPAD + am) << 2);
        #pragma unroll
        for (int i = 0; i < 8; i++) {
            bool p = kA && (m0 + am + (i << 4)) < M;
            cpa4(dA + ((i << 4) << 2), gA + ((long)(i << 4)) * K, p);
        }
        bool kB = (k0 + bk) < K;
        const float* gB = B + (long)(k0 + bk) * N + n0;
        uint32_t dB = sB[s] + ((bk * TPAD) << 2);
        cpa16(dB + ((bq << 2) << 2), gB + (bq << 2), kB);
        cpa16(dB + ((64 + (bq << 2)) << 2), gB + 64 + (bq << 2), kB);
    };

    issue(0, 0);
    asm volatile("cp.async.commit_group;");

    for (int it = 0; it < nIter; it++) {
        int cur = it & 1;
        if (it + 1 < nIter) issue(it + 1, cur ^ 1);
        asm volatile("cp.async.commit_group;");
        asm volatile("cp.async.wait_group 1;");
        __syncthreads();

        #pragma unroll
        for (int kk = 0; kk < TBK; kk += 8) {
            uint32_t a[2][4], b[8][2];
            #pragma unroll
            for (int i = 0; i < 2; i++) {
                int mb = warp_m + (i << 4);
                a[i][0] = __float_as_uint(As[cur][kk + r][mb + g]);
                a[i][1] = __float_as_uint(As[cur][kk + r][mb + g + 8]);
                a[i][2] = __float_as_uint(As[cur][kk + r + 4][mb + g]);
                a[i][3] = __float_as_uint(As[cur][kk + r + 4][mb + g + 8]);
            }
            #pragma unroll
            for (int j = 0; j < 8; j++) {
                int nb = warp_n + (j << 3);
                b[j][0] = __float_as_uint(Bs[cur][kk + r][nb + g]);
                b[j][1] = __float_as_uint(Bs[cur][kk + r + 4][nb + g]);
            }
            #pragma unroll
            for (int i = 0; i < 2; i++)
                #pragma unroll
                for (int j = 0; j < 8; j++)
                    asm volatile(
                        "mma.sync.aligned.m16n8k8.row.col.f32.tf32.tf32.f32 "
                        "{%0,%1,%2,%3}, {%4,%5,%6,%7}, {%8,%9}, {%0,%1,%2,%3};"
                        : "+f"(c[i][j][0]), "+f"(c[i][j][1]), "+f"(c[i][j][2]), "+f"(c[i][j][3])
                        : "r"(a[i][0]), "r"(a[i][1]), "r"(a[i][2]), "r"(a[i][3]),
                          "r"(b[j][0]), "r"(b[j][1]));
        }
        __syncthreads();
    }

    #pragma unroll
    for (int i = 0; i < 2; i++) {
        #pragma unroll
        for (int j = 0; j < 8; j++) {
            int col = n0 + warp_n + (j << 3) + (r << 1);
            int row0 = m0 + warp_m + (i << 4) + g;
            if (row0 < M) {
                C[(long)row0 * N + col]     = c[i][j][0];
                C[(long)row0 * N + col + 1] = c[i][j][1];
            }
            int row1 = row0 + 8;
            if (row1 < M) {
                C[(long)row1 * N + col]     = c[i][j][2];
                C[(long)row1 * N + col + 1] = c[i][j][3];
            }
        }
    }
}

// GEMV: out[m] = dot(A[m,:K], w[:K]), K multiple of 128, float4.
__global__ void gemv_kernel(const float* __restrict__ A, const float* __restrict__ w,
                            float* __restrict__ out, int M, int K) {
    int gt = blockIdx.x * blockDim.x + threadIdx.x;
    int row = gt >> 5, lane = gt & 31;
    if (row >= M) return;
    const float4* a4 = (const float4*)(A + (long)row * K);
    const float4* w4 = (const float4*)w;
    int K4 = K >> 2;
    float s = 0.f;
    for (int k = lane; k < K4; k += 32) {
        float4 a = a4[k], b = w4[k];
        s = fmaf(a.x, b.x, s); s = fmaf(a.y, b.y, s);
        s = fmaf(a.z, b.z, s); s = fmaf(a.w, b.w, s);
    }
    #pragma unroll
    for (int o = 16; o; o >>= 1) s += __shfl_xor_sync(0xffffffffu, s, o);
    if (lane == 0) out[row] = s;
}

// ---------------- FUSED logits + online-softmax + mean aggregate ----------------

__device__ __forceinline__ float leaky02(float v) { return v > 0.f ? v : 0.2f * v; }

// H = 2 (layer 1)
__global__ __launch_bounds__(256) void fused_agg_h2(
    const float* __restrict__ xl, const float* __restrict__ xr,
    const float* __restrict__ att,
    const int* __restrict__ rowptr, const int* __restrict__ csrsrc,
    const float* __restrict__ bias, float* __restrict__ out, int N) {
    int node = blockIdx.x * 8 + (threadIdx.x >> 5);
    if (node >= N) return;
    int lane = threadIdx.x & 31;
    const int HC4 = 64;

    const float4* xl4 = (const float4*)xl;
    const float4* xr4 = (const float4*)xr;
    const float4* at4 = (const float4*)att;
    const float4* b4  = (const float4*)bias;
    float4* out4 = (float4*)out;

    long base = (long)node * HC4 + lane;

    float4 xrv0 = xr4[base],      xrv1 = xr4[base + 32];
    float4 atv0 = at4[lane],      atv1 = at4[32 + lane];
    float4 bb0  = b4[lane],       bb1  = b4[32 + lane];

    int beg = rowptr[node], end = rowptr[node + 1];
    if (beg == end) {
        out4[base] = bb0;
        out4[base + 32] = bb1;
        return;
    }

    float m0 = -1e30f, s0 = 0.f, m1 = -1e30f, s1 = 0.f;
    float4 acc0 = make_float4(0.f, 0.f, 0.f, 0.f);
    float4 acc1 = make_float4(0.f, 0.f, 0.f, 0.f);

    for (int e = beg; e < end; e++) {
        int srcn = __ldg(&csrsrc[e]);
        long sb = (long)srcn * HC4 + lane;
        float4 v0 = xl4[sb], v1 = xl4[sb + 32];
        float t0, t1;
        t0  = leaky02(v0.x + xrv0.x) * atv0.x;
        t0 += leaky02(v0.y + xrv0.y) * atv0.y;
        t0 += leaky02(v0.z + xrv0.z) * atv0.z;
        t0 += leaky02(v0.w + xrv0.w) * atv0.w;
        t1  = leaky02(v1.x + xrv1.x) * atv1.x;
        t1 += leaky02(v1.y + xrv1.y) * atv1.y;
        t1 += leaky02(v1.z + xrv1.z) * atv1.z;
        t1 += leaky02(v1.w + xrv1.w) * atv1.w;
        #pragma unroll
        for (int o = 16; o; o >>= 1) {
            t0 += __shfl_xor_sync(0xffffffffu, t0, o);
            t1 += __shfl_xor_sync(0xffffffffu, t1, o);
        }
        {
            float nm = fmaxf(m0, t0);
            float sc = __expf(m0 - nm);
            float w  = __expf(t0 - nm);
            s0 = s0 * sc + w;
            acc0.x = acc0.x * sc + w * v0.x;
            acc0.y = acc0.y * sc + w * v0.y;
            acc0.z = acc0.z * sc + w * v0.z;
            acc0.w = acc0.w * sc + w * v0.w;
            m0 = nm;
        }
        {
            float nm = fmaxf(m1, t1);
            float sc = __expf(m1 - nm);
            float w  = __expf(t1 - nm);
            s1 = s1 * sc + w;
            acc1.x = acc1.x * sc + w * v1.x;
            acc1.y = acc1.y * sc + w * v1.y;
            acc1.z = acc1.z * sc + w * v1.z;
            acc1.w = acc1.w * sc + w * v1.w;
            m1 = nm;
        }
    }

    float degf = (float)(end - beg);
    {
        float inv = 1.f / (s0 * degf);
        float4 o;
        o.x = acc0.x * inv + bb0.x;
        o.y = acc0.y * inv + bb0.y;
        o.z = acc0.z * inv + bb0.z;
        o.w = acc0.w * inv + bb0.w;
        out4[base] = o;
    }
    {
        float inv = 1.f / (s1 * degf);
        float4 o;
        o.x = acc1.x * inv + bb1.x;
        o.y = acc1.y * inv + bb1.y;
        o.z = acc1.z * inv + bb1.z;
        o.w = acc1.w * inv + bb1.w;
        out4[base + 32] = o;
    }
}

// H = 1 (layer 2)
__global__ __launch_bounds__(256) void fused_agg_h1(
    const float* __restrict__ xl, const float* __restrict__ xr,
    const float* __restrict__ att,
    const int* __restrict__ rowptr, const int* __restrict__ csrsrc,
    const float* __restrict__ bias, float* __restrict__ out, int N) {
    int node = blockIdx.x * 8 + (threadIdx.x >> 5);
    if (node >= N) return;
    int lane = threadIdx.x & 31;
    const int HC4 = 32;

    const float4* xl4 = (const float4*)xl;
    const float4* xr4 = (const float4*)xr;
    const float4* at4 = (const float4*)att;
    const float4* b4  = (const float4*)bias;
    float4* out4 = (float4*)out;

    long base = (long)node * HC4 + lane;

    float4 xrv = xr4[base];
    float4 atv = at4[lane];
    float4 bb  = b4[lane];

    int beg = rowptr[node], end = rowptr[node + 1];
    if (beg == end) { out4[base] = bb; return; }

    float m = -1e30f, s = 0.f;
    float4 acc = make_float4(0.f, 0.f, 0.f, 0.f);

    for (int e = beg; e < end; e++) {
        int srcn = __ldg(&csrsrc[e]);
        float4 v = xl4[(long)srcn * HC4 + lane];
        float t;
        t  = leaky02(v.x + xrv.x) * atv.x;
        t += leaky02(v.y + xrv.y) * atv.y;
        t += leaky02(v.z + xrv.z) * atv.z;
        t += leaky02(v.w + xrv.w) * atv.w;
        #pragma unroll
        for (int o = 16; o; o >>= 1) t += __shfl_xor_sync(0xffffffffu, t, o);
        float nm = fmaxf(m, t);
        float sc = __expf(m - nm);
        float w  = __expf(t - nm);
        s = s * sc + w;
        acc.x = acc.x * sc + w * v.x;
        acc.y = acc.y * sc + w * v.y;
        acc.z = acc.z * sc + w * v.z;
        acc.w = acc.w * sc + w * v.w;
        m = nm;
    }

    float inv = 1.f / (s * (float)(end - beg));
    float4 o;
    o.x = acc.x * inv + bb.x;
    o.y = acc.y * inv + bb.y;
    o.z = acc.z * inv + bb.z;
    o.w = acc.w * inv + bb.w;
    out4[base] = o;
}

// Layer 3 fused (C=1): thread per node, scalar online softmax.
__global__ void fused_agg3_kernel(const float* __restrict__ xl, const float* __restrict__ xr,
                                  const float* __restrict__ att,
                                  const int* __restrict__ rowptr, const int* __restrict__ csrsrc,
                                  const float* __restrict__ bias, float* __restrict__ out, int N) {
    int node = blockIdx.x * blockDim.x + threadIdx.x;
    if (node >= N) return;
    int beg = rowptr[node], end = rowptr[node + 1];
    float b0 = bias[0];
    if (beg == end) { out[node] = b0; return; }
    float a0 = att[0];
    float xrn = xr[node];
    float m = -1e30f, s = 0.f, acc = 0.f;
    for (int e = beg; e < end; e++) {
        float v = xl[csrsrc[e]];
        float t = leaky02(v + xrn) * a0;
        float nm = fmaxf(m, t);
        float sc = __expf(m - nm);
        float w  = __expf(t - nm);
        s = s * sc + w;
        acc = acc * sc + w * v;
        m = nm;
    }
    out[node] = acc / (s * (float)(end - beg)) + b0;
}

// ---------------- Output gather ----------------

__global__ void gather_kernel(const float* __restrict__ h3, const float* __restrict__ y,
                              const int* __restrict__ tidx, int nt, int N,
                              float* __restrict__ out, int both) {
    int i = blockIdx.x * blockDim.x + threadIdx.x;
    if (i >= nt) return;
    int t = tidx[i];
    if (t < 0) t = 0;
    if (t >= N) t = N - 1;
    out[i] = 1.f / (1.f + __expf(-h3[t]));
    if (both) out[nt + i] = y[t];
}

// ---------------- Launch ----------------

extern "C" void kernel_launch(void* const* d_in, const int* in_sizes, int n_in,
                              void* d_out, int out_size) {
    const float* x    = (const float*)d_in[0];
    const int*   ei   = (const int*)d_in[1];
    const float* y    = (const float*)d_in[2];
    const int*   tidx = (const int*)d_in[3];
    const float* W1l = (const float*)d_in[4];
    const float* W1r = (const float*)d_in[5];
    const float* a1  = (const float*)d_in[6];
    const float* b1  = (const float*)d_in[7];
    const float* W2l = (const float*)d_in[8];
    const float* W2r = (const float*)d_in[9];
    const float* a2  = (const float*)d_in[10];
    const float* b2  = (const float*)d_in[11];
    const float* W3l = (const float*)d_in[12];
    const float* W3r = (const float*)d_in[13];
    const float* a3  = (const float*)d_in[14];
    const float* b3  = (const float*)d_in[15];

    int N  = in_sizes[2];
    int E  = in_sizes[1] / 2;
    int NT = in_sizes[3];
    int IN = in_sizes[0] / N;

    const int* src = ei;
    const int* dst = ei + E;

    float *p_xl, *p_xr, *p_h;
    int *p_rowptr, *p_cursor, *p_deg, *p_csrsrc;
    cudaGetSymbolAddress((void**)&p_xl, g_xl);
    cudaGetSymbolAddress((void**)&p_xr, g_xr);
    cudaGetSymbolAddress((void**)&p_h,  g_h);
    cudaGetSymbolAddress((void**)&p_rowptr, g_rowptr);
    cudaGetSymbolAddress((void**)&p_cursor, g_cursor);
    cudaGetSymbolAddress((void**)&p_deg,    g_deg);
    cudaGetSymbolAddress((void**)&p_csrsrc, g_csrsrc);

    // ---- CSR build (kernel-only) ----
    zero_kernel<<<(N + 255) / 256, 256>>>(p_deg, N);
    hist_kernel<<<(E + 255) / 256, 256>>>(dst, E, N, p_deg);
    scan_kernel<<<1, 1024>>>(p_deg, p_rowptr, p_cursor, N);
    scatter_kernel<<<(E + 255) / 256, 256>>>(src, dst, E, N, p_cursor, p_csrsrc);

    int gm = (N + TBM - 1) / TBM;
    int gn = (N + 7) / 8;

    // ---- Layer 1: 129 -> 256 (H=2, C=128) ----
    {
        dim3 g(256 / TBN, gm, 2);
        gemm_tf32_kernel<<<g, 256>>>(x, W1l, W1r, p_xl, p_xr, N, IN, 256);
        fused_agg_h2<<<gn, 256>>>(p_xl, p_xr, a1, p_rowptr, p_csrsrc, b1, p_h, N);
    }

    // ---- Layer 2: 256 -> 128 (H=1, C=128) ----
    {
        dim3 g(128 / TBN, gm, 2);
        gemm_tf32_kernel<<<g, 256>>>(p_h, W2l, W2r, p_xl, p_xr, N, 256, 128);
        fused_agg_h1<<<gn, 256>>>(p_xl, p_xr, a2, p_rowptr, p_csrsrc, b2, p_h, N);
    }

    // ---- Layer 3: 128 -> 1 (H=1, C=1) ----
    {
        gemv_kernel<<<(N * 32 + 255) / 256, 256>>>(p_h, W3l, p_xl, N, 128);
        gemv_kernel<<<(N * 32 + 255) / 256, 256>>>(p_h, W3r, p_xr, N, 128);
        fused_agg3_kernel<<<(N + 255) / 256, 256>>>(p_xl, p_xr, a3, p_rowptr, p_csrsrc, b3, p_h, N);
    }

    // ---- Output: pred[train_idx], y[train_idx] ----
    int both = (out_size >= 2 * NT) ? 1 : 0;
    gather_kernel<<<(NT + 255) / 256, 256>>>(p_h, y, tidx, NT, N, (float*)d_out, both);
}